// round 3
// baseline (speedup 1.0000x reference)
#include <cuda_runtime.h>
#include <cstdint>
#include <cfloat>

// Problem constants (fixed shapes for MergeNN_38903813767173)
#define B_ 2048
#define N_ 20000
#define D_ 64
#define DY_ 32
#define L_ 100
#define ETA_ 0.01f

#define TJ 64                 // query columns per block
#define TI 64                 // dataset rows per chunk
#define SLABROWS 832          // rows per slab (13 chunks of 64)
#define NSLAB 25              // ceil(20000/832)

#define SSP 65                // row-major star/f chunk stride (conflict-free scalar reads)
#define XSP 68                // k-major x tile stride (16B-aligned rows)
#define ESP 68                // es tile stride
#define MSP 68                // multT stride

typedef unsigned long long ull;

__device__ __forceinline__ ull pack2(float lo, float hi) {
    ull r; asm("mov.b64 %0, {%1, %2};" : "=l"(r) : "f"(lo), "f"(hi)); return r;
}
__device__ __forceinline__ void unpack2(ull v, float& lo, float& hi) {
    asm("mov.b64 {%0, %1}, %2;" : "=f"(lo), "=f"(hi) : "l"(v));
}
__device__ __forceinline__ void ffma2(ull& d, ull a, ull b) {
    asm("fma.rn.f32x2 %0, %1, %2, %0;" : "+l"(d) : "l"(a), "l"(b));
}

// ---------------- scratch (device globals; no allocations allowed) ----------
__device__ float g_nx[B_];
__device__ float g_ns[N_];
__device__ float g_nf1[N_];
__device__ float g_nf2[N_];
__device__ int   g_match[B_];

__device__ float g_esum_part[NSLAB][B_];
__device__ float g_acc1_part[NSLAB][B_][D_];
__device__ float g_acc2_part[NSLAB][B_][D_];

__device__ float g_xt1[B_][D_];
__device__ float g_xt2[B_][D_];
__device__ float g_nxt1[B_];
__device__ float g_nxt2[B_];
__device__ int   g_yidx1[B_];
__device__ int   g_yidx2[B_];

__device__ float g_num1_part[NSLAB][B_][DY_];
__device__ float g_num2_part[NSLAB][B_][DY_];
__device__ float g_den1_part[NSLAB][B_];
__device__ float g_den2_part[NSLAB][B_];

// ---------------- K0: squared norms + match init -----------------------------
__global__ void k_prep(const float* __restrict__ x, const float* __restrict__ star,
                       const float* __restrict__ f1, const float* __restrict__ f2) {
    int gid = blockIdx.x * blockDim.x + threadIdx.x;
    const float* src;
    float* dst;
    if (gid < B_) {
        g_match[gid] = 0x7fffffff;
        src = x + gid * D_;        dst = &g_nx[gid];
    } else if (gid < B_ + N_) {
        int r = gid - B_;          src = star + r * D_; dst = &g_ns[r];
    } else if (gid < B_ + 2 * N_) {
        int r = gid - B_ - N_;     src = f1 + r * D_;   dst = &g_nf1[r];
    } else if (gid < B_ + 3 * N_) {
        int r = gid - B_ - 2 * N_; src = f2 + r * D_;   dst = &g_nf2[r];
    } else {
        return;
    }
    float s = 0.f;
    const float4* p = reinterpret_cast<const float4*>(src);
#pragma unroll
    for (int i = 0; i < 16; i++) {
        float4 v = p[i];
        s += v.x * v.x + v.y * v.y + v.z * v.z + v.w * v.w;
    }
    *dst = s;
}

// ---------------- K1: phase A — e_star, esum, feats^T @ e_star ---------------
struct __align__(16) SmemA {
    float xst[D_][XSP];   // x tile, k-major: xst[k][j]
    float nxs[TJ];
    float ss[TI][SSP];    // star chunk, row-major (padded)
    float nss[TI];
    float f1s[TI][D_];
    float f2s[TI][D_];
    float es[TI][ESP];    // e_star tile [i][j]
};

__global__ __launch_bounds__(256, 2)
void k_phaseA(const float* __restrict__ x, const float* __restrict__ star,
              const float* __restrict__ f1, const float* __restrict__ f2) {
    extern __shared__ char raw_[];
    SmemA& sm = *reinterpret_cast<SmemA*>(raw_);
    const int tid    = threadIdx.x;
    const int j0     = blockIdx.x * TJ;
    const int slab   = blockIdx.y;
    const int ibase  = slab * SLABROWS;
    const int iend   = min(ibase + SLABROWS, N_);
    const int nchunk = (iend - ibase + TI - 1) / TI;

    // x tile (k-major), once per block
    for (int idx = tid; idx < TJ * 16; idx += 256) {
        int j = idx >> 4, k4 = (idx & 15) * 4;
        float4 v = *reinterpret_cast<const float4*>(x + (j0 + j) * D_ + k4);
        sm.xst[k4 + 0][j] = v.x; sm.xst[k4 + 1][j] = v.y;
        sm.xst[k4 + 2][j] = v.z; sm.xst[k4 + 3][j] = v.w;
    }
    if (tid < TJ) sm.nxs[tid] = g_nx[j0 + tid];

    const int col8 = (tid & 7) * 8;     // distance: 8 cols
    const int row2 = (tid >> 3) * 2;    // distance: 2 rows
    const int jc2  = (tid & 31) * 2;    // accumulate: 2 cols
    const int db8  = (tid >> 5) * 8;    // accumulate: 8 d's

    ull acc1[2][4], acc2[2][4];
    float esm0 = 0.f, esm1 = 0.f;
#pragma unroll
    for (int a = 0; a < 2; a++)
#pragma unroll
        for (int b = 0; b < 4; b++) { acc1[a][b] = 0ull; acc2[a][b] = 0ull; }

    float4 pf_s[4], pf_a[4], pf_b[4];
    float  pf_n;
    const int ld_r  = tid >> 4;
    const int ld_k4 = (tid & 15) * 4;

    // prologue: load chunk 0
#pragma unroll
    for (int q = 0; q < 4; q++) {
        int r = ld_r + q * 16;
        int gi = min(ibase + r, N_ - 1);
        pf_s[q] = *reinterpret_cast<const float4*>(star + gi * D_ + ld_k4);
        pf_a[q] = *reinterpret_cast<const float4*>(f1 + gi * D_ + ld_k4);
        pf_b[q] = *reinterpret_cast<const float4*>(f2 + gi * D_ + ld_k4);
    }
    pf_n = (tid < TI) ? g_ns[min(ibase + tid, N_ - 1)] : 0.f;
#pragma unroll
    for (int q = 0; q < 4; q++) {
        int r = ld_r + q * 16;
        sm.ss[r][ld_k4 + 0] = pf_s[q].x; sm.ss[r][ld_k4 + 1] = pf_s[q].y;
        sm.ss[r][ld_k4 + 2] = pf_s[q].z; sm.ss[r][ld_k4 + 3] = pf_s[q].w;
        *reinterpret_cast<float4*>(&sm.f1s[r][ld_k4]) = pf_a[q];
        *reinterpret_cast<float4*>(&sm.f2s[r][ld_k4]) = pf_b[q];
    }
    if (tid < TI) sm.nss[tid] = pf_n;
    __syncthreads();

    for (int c = 0; c < nchunk; c++) {
        const int i0 = ibase + c * TI;

        // --- distance micro-kernel: 2 rows x 8 cols, packed f32x2 ---
        ull a_[2][4];
#pragma unroll
        for (int r = 0; r < 2; r++)
#pragma unroll
            for (int cc = 0; cc < 4; cc++) a_[r][cc] = 0ull;

#pragma unroll 8
        for (int k = 0; k < D_; k++) {
            ulonglong2 xq0 = *reinterpret_cast<const ulonglong2*>(&sm.xst[k][col8]);
            ulonglong2 xq1 = *reinterpret_cast<const ulonglong2*>(&sm.xst[k][col8 + 4]);
            float s0 = sm.ss[row2][k];
            float s1 = sm.ss[row2 + 1][k];
            ull sp0 = pack2(s0, s0), sp1 = pack2(s1, s1);
            ffma2(a_[0][0], sp0, xq0.x); ffma2(a_[0][1], sp0, xq0.y);
            ffma2(a_[0][2], sp0, xq1.x); ffma2(a_[0][3], sp0, xq1.y);
            ffma2(a_[1][0], sp1, xq0.x); ffma2(a_[1][1], sp1, xq0.y);
            ffma2(a_[1][2], sp1, xq1.x); ffma2(a_[1][3], sp1, xq1.y);
        }

        {
            float4 nxa = *reinterpret_cast<const float4*>(&sm.nxs[col8]);
            float4 nxb = *reinterpret_cast<const float4*>(&sm.nxs[col8 + 4]);
            float nx[8] = {nxa.x, nxa.y, nxa.z, nxa.w, nxb.x, nxb.y, nxb.z, nxb.w};
#pragma unroll
            for (int r = 0; r < 2; r++) {
                int gi = i0 + row2 + r;
                bool valid = gi < N_;
                float ns = sm.nss[row2 + r];
                float ev[8];
#pragma unroll
                for (int c2 = 0; c2 < 4; c2++) {
                    float d0, d1;
                    unpack2(a_[r][c2], d0, d1);
                    float r0 = ns + nx[2 * c2]     - 2.f * d0;
                    float r1 = ns + nx[2 * c2 + 1] - 2.f * d1;
                    if (valid && r0 <= 0.f) atomicMin(&g_match[j0 + col8 + 2 * c2], gi);
                    if (valid && r1 <= 0.f) atomicMin(&g_match[j0 + col8 + 2 * c2 + 1], gi);
                    ev[2 * c2]     = valid ? __expf(-fmaxf(r0, 0.f)) : 0.f;
                    ev[2 * c2 + 1] = valid ? __expf(-fmaxf(r1, 0.f)) : 0.f;
                }
                *reinterpret_cast<float4*>(&sm.es[row2 + r][col8]) =
                    make_float4(ev[0], ev[1], ev[2], ev[3]);
                *reinterpret_cast<float4*>(&sm.es[row2 + r][col8 + 4]) =
                    make_float4(ev[4], ev[5], ev[6], ev[7]);
            }
        }

        // prefetch next chunk into registers (latency hidden under accumulate)
        if (c + 1 < nchunk) {
            int i0n = i0 + TI;
#pragma unroll
            for (int q = 0; q < 4; q++) {
                int r = ld_r + q * 16;
                int gi = min(i0n + r, N_ - 1);
                pf_s[q] = *reinterpret_cast<const float4*>(star + gi * D_ + ld_k4);
                pf_a[q] = *reinterpret_cast<const float4*>(f1 + gi * D_ + ld_k4);
                pf_b[q] = *reinterpret_cast<const float4*>(f2 + gi * D_ + ld_k4);
            }
            pf_n = (tid < TI) ? g_ns[min(i0n + tid, N_ - 1)] : 0.f;
        }
        __syncthreads();   // es ready

        // --- accumulate: acc[j][d] += f[i][d] * e[i][j], 2j x 8d ---
#pragma unroll 4
        for (int ii = 0; ii < TI; ii++) {
            float2 e2 = *reinterpret_cast<const float2*>(&sm.es[ii][jc2]);
            ull er0 = pack2(e2.x, e2.x), er1 = pack2(e2.y, e2.y);
            ulonglong2 fq0 = *reinterpret_cast<const ulonglong2*>(&sm.f1s[ii][db8]);
            ulonglong2 fq1 = *reinterpret_cast<const ulonglong2*>(&sm.f1s[ii][db8 + 4]);
            ffma2(acc1[0][0], er0, fq0.x); ffma2(acc1[0][1], er0, fq0.y);
            ffma2(acc1[0][2], er0, fq1.x); ffma2(acc1[0][3], er0, fq1.y);
            ffma2(acc1[1][0], er1, fq0.x); ffma2(acc1[1][1], er1, fq0.y);
            ffma2(acc1[1][2], er1, fq1.x); ffma2(acc1[1][3], er1, fq1.y);
            ulonglong2 gq0 = *reinterpret_cast<const ulonglong2*>(&sm.f2s[ii][db8]);
            ulonglong2 gq1 = *reinterpret_cast<const ulonglong2*>(&sm.f2s[ii][db8 + 4]);
            ffma2(acc2[0][0], er0, gq0.x); ffma2(acc2[0][1], er0, gq0.y);
            ffma2(acc2[0][2], er0, gq1.x); ffma2(acc2[0][3], er0, gq1.y);
            ffma2(acc2[1][0], er1, gq0.x); ffma2(acc2[1][1], er1, gq0.y);
            ffma2(acc2[1][2], er1, gq1.x); ffma2(acc2[1][3], er1, gq1.y);
            if (db8 == 0) { esm0 += e2.x; esm1 += e2.y; }
        }
        __syncthreads();   // smem consumers done

        if (c + 1 < nchunk) {
#pragma unroll
            for (int q = 0; q < 4; q++) {
                int r = ld_r + q * 16;
                sm.ss[r][ld_k4 + 0] = pf_s[q].x; sm.ss[r][ld_k4 + 1] = pf_s[q].y;
                sm.ss[r][ld_k4 + 2] = pf_s[q].z; sm.ss[r][ld_k4 + 3] = pf_s[q].w;
                *reinterpret_cast<float4*>(&sm.f1s[r][ld_k4]) = pf_a[q];
                *reinterpret_cast<float4*>(&sm.f2s[r][ld_k4]) = pf_b[q];
            }
            if (tid < TI) sm.nss[tid] = pf_n;
            __syncthreads();
        }
    }

#pragma unroll
    for (int j = 0; j < 2; j++) {
        int jj = j0 + jc2 + j;
        float o[8];
        unpack2(acc1[j][0], o[0], o[1]); unpack2(acc1[j][1], o[2], o[3]);
        unpack2(acc1[j][2], o[4], o[5]); unpack2(acc1[j][3], o[6], o[7]);
        *reinterpret_cast<float4*>(&g_acc1_part[slab][jj][db8]) =
            make_float4(o[0], o[1], o[2], o[3]);
        *reinterpret_cast<float4*>(&g_acc1_part[slab][jj][db8 + 4]) =
            make_float4(o[4], o[5], o[6], o[7]);
        unpack2(acc2[j][0], o[0], o[1]); unpack2(acc2[j][1], o[2], o[3]);
        unpack2(acc2[j][2], o[4], o[5]); unpack2(acc2[j][3], o[6], o[7]);
        *reinterpret_cast<float4*>(&g_acc2_part[slab][jj][db8]) =
            make_float4(o[0], o[1], o[2], o[3]);
        *reinterpret_cast<float4*>(&g_acc2_part[slab][jj][db8 + 4]) =
            make_float4(o[4], o[5], o[6], o[7]);
    }
    if (db8 == 0) {
        g_esum_part[slab][j0 + jc2 + 0] = esm0;
        g_esum_part[slab][j0 + jc2 + 1] = esm1;
    }
}

// ---------------- K2: middle — xt, y = xt@W+b, argmin label ------------------
__global__ __launch_bounds__(128)
void k_mid(const float* __restrict__ f1, const float* __restrict__ f2,
           const float* __restrict__ W1, const float* __restrict__ b1,
           const float* __restrict__ W2, const float* __restrict__ b2,
           const float* __restrict__ u1, const float* __restrict__ u2) {
    int j = blockIdx.x;
    int t = threadIdx.x;   // 128 threads

    __shared__ float xts[D_];
    __shared__ float ys[DY_];
    __shared__ float esum_s;
    __shared__ float ny_s;
    __shared__ float redv[128];
    __shared__ int   redi[128];

    int  mi = g_match[j];
    bool hm = (mi != 0x7fffffff);
    if (t == 0) {
        float s = 0.f;
        for (int k = 0; k < NSLAB; k++) s += g_esum_part[k][j];
        esum_s = s;
    }
    __syncthreads();

    for (int br = 0; br < 2; br++) {
        const float* f  = br ? f2 : f1;
        const float* W  = br ? W2 : W1;
        const float* bb = br ? b2 : b1;
        const float* u  = br ? u2 : u1;

        if (t < D_) {
            float a = 0.f;
            if (br) { for (int k = 0; k < NSLAB; k++) a += g_acc2_part[k][j][t]; }
            else    { for (int k = 0; k < NSLAB; k++) a += g_acc1_part[k][j][t]; }
            float v = hm ? f[mi * D_ + t] : a / esum_s;
            xts[t] = v;
            if (br) g_xt2[j][t] = v; else g_xt1[j][t] = v;
        }
        __syncthreads();
        if (t == 0) {
            float s = 0.f;
            for (int d = 0; d < D_; d++) s += xts[d] * xts[d];
            if (br) g_nxt2[j] = s; else g_nxt1[j] = s;
        }
        if (t < DY_) {
            float a = bb[t];
            for (int d = 0; d < D_; d++) a += xts[d] * W[d * DY_ + t];
            ys[t] = a;
        }
        __syncthreads();
        if (t == 0) {
            float s = 0.f;
            for (int dy = 0; dy < DY_; dy++) s += ys[dy] * ys[dy];
            ny_s = s;
        }
        __syncthreads();

        float v = FLT_MAX;
        int   vi = 0x7fffffff;
        if (t < L_) {
            float nu = 0.f, dot = 0.f;
            for (int dy = 0; dy < DY_; dy++) {
                float uu = u[t * DY_ + dy];
                nu += uu * uu;
                dot += uu * ys[dy];
            }
            v = fmaxf(ny_s + nu - 2.f * dot, 0.f);
            vi = t;
        }
        redv[t] = v; redi[t] = vi;
        __syncthreads();
        for (int off = 64; off > 0; off >>= 1) {
            if (t < off) {
                float v2 = redv[t + off]; int i2 = redi[t + off];
                if (v2 < redv[t] || (v2 == redv[t] && i2 < redi[t])) {
                    redv[t] = v2; redi[t] = i2;
                }
            }
            __syncthreads();
        }
        if (t == 0) { if (br) g_yidx2[j] = redi[0]; else g_yidx1[j] = redi[0]; }
        __syncthreads();
    }
}

// ---------------- K3: phase C — e2, labels^T @ e2 ---------------------------
struct __align__(16) SmemC {
    float multT[L_][MSP]; // exp(-eta*ld[l][yidx[j]]) per block column
    float xtst[D_][XSP];  // xt tile, k-major
    float nxts[TJ];
    int   yidxs[TJ];
    float fs[TI][SSP];    // feature chunk, row-major (padded)
    float nfs[TI];
    int   lidxs[TI];
    float sls[TI][DY_];   // star_labels chunk
    float es[TI][ESP];
};

__global__ __launch_bounds__(256, 2)
void k_phaseC(const float* __restrict__ f1, const float* __restrict__ f2,
              const float* __restrict__ slb,
              const float* __restrict__ ld1, const float* __restrict__ ld2,
              const int* __restrict__ li1, const int* __restrict__ li2) {
    extern __shared__ char raw_[];
    SmemC& sm = *reinterpret_cast<SmemC*>(raw_);
    const int tid    = threadIdx.x;
    const int j0     = blockIdx.x * TJ;
    const int slab   = blockIdx.y;
    const int br     = blockIdx.z;
    const int ibase  = slab * SLABROWS;
    const int iend   = min(ibase + SLABROWS, N_);
    const int nchunk = (iend - ibase + TI - 1) / TI;

    const float* f   = br ? f2 : f1;
    const float* ld  = br ? ld2 : ld1;
    const int*   li  = br ? li2 : li1;
    const float* nf  = br ? g_nf2 : g_nf1;
    const float (*xt)[D_] = br ? g_xt2 : g_xt1;
    const float* nxt = br ? g_nxt2 : g_nxt1;
    const int*   yix = br ? g_yidx2 : g_yidx1;
    float (*nump)[B_][DY_] = br ? g_num2_part : g_num1_part;
    float (*denp)[B_]      = br ? g_den2_part : g_den1_part;

    for (int idx = tid; idx < TJ * 16; idx += 256) {
        int j = idx >> 4, k4 = (idx & 15) * 4;
        float4 v = *reinterpret_cast<const float4*>(&xt[j0 + j][k4]);
        sm.xtst[k4 + 0][j] = v.x; sm.xtst[k4 + 1][j] = v.y;
        sm.xtst[k4 + 2][j] = v.z; sm.xtst[k4 + 3][j] = v.w;
    }
    if (tid < TJ) { sm.nxts[tid] = nxt[j0 + tid]; sm.yidxs[tid] = yix[j0 + tid]; }

    const int col8 = (tid & 7) * 8;
    const int row2 = (tid >> 3) * 2;
    const int jc2  = (tid & 31) * 2;
    const int dy4  = (tid >> 5) * 4;
    const int ld_r  = tid >> 4;
    const int ld_k4 = (tid & 15) * 4;

    ull accn[2][2];
    float dn0 = 0.f, dn1 = 0.f;
    accn[0][0] = accn[0][1] = accn[1][0] = accn[1][1] = 0ull;

    float4 pf_f[4], pf_sl[2];
    float  pf_n; int pf_l;

    // prologue: load chunk 0 into regs (no smem deps)
#pragma unroll
    for (int q = 0; q < 4; q++) {
        int gi = min(ibase + ld_r + q * 16, N_ - 1);
        pf_f[q] = *reinterpret_cast<const float4*>(f + gi * D_ + ld_k4);
    }
#pragma unroll
    for (int q = 0; q < 2; q++) {
        int idx = tid + q * 256, r = idx >> 3, k4 = (idx & 7) * 4;
        int gi = min(ibase + r, N_ - 1);
        pf_sl[q] = *reinterpret_cast<const float4*>(slb + gi * DY_ + k4);
    }
    pf_n = (tid < TI) ? nf[min(ibase + tid, N_ - 1)] : 0.f;
    pf_l = (tid < TI) ? li[min(ibase + tid, N_ - 1)] : 0;

    __syncthreads();   // yidxs visible

    // build multT: exp(-eta * ld[l][yidx[j]]) — 100x64, once per block
    for (int idx = tid; idx < L_ * TJ; idx += 256) {
        int l = idx >> 6, j = idx & 63;
        sm.multT[l][j] = __expf(-ETA_ * ld[l * L_ + sm.yidxs[j]]);
    }
    // store chunk 0
#pragma unroll
    for (int q = 0; q < 4; q++) {
        int r = ld_r + q * 16;
        sm.fs[r][ld_k4 + 0] = pf_f[q].x; sm.fs[r][ld_k4 + 1] = pf_f[q].y;
        sm.fs[r][ld_k4 + 2] = pf_f[q].z; sm.fs[r][ld_k4 + 3] = pf_f[q].w;
    }
#pragma unroll
    for (int q = 0; q < 2; q++) {
        int idx = tid + q * 256, r = idx >> 3, k4 = (idx & 7) * 4;
        *reinterpret_cast<float4*>(&sm.sls[r][k4]) = pf_sl[q];
    }
    if (tid < TI) { sm.nfs[tid] = pf_n; sm.lidxs[tid] = pf_l; }
    __syncthreads();

    for (int c = 0; c < nchunk; c++) {
        const int i0 = ibase + c * TI;

        ull a_[2][4];
#pragma unroll
        for (int r = 0; r < 2; r++)
#pragma unroll
            for (int cc = 0; cc < 4; cc++) a_[r][cc] = 0ull;

#pragma unroll 8
        for (int k = 0; k < D_; k++) {
            ulonglong2 xq0 = *reinterpret_cast<const ulonglong2*>(&sm.xtst[k][col8]);
            ulonglong2 xq1 = *reinterpret_cast<const ulonglong2*>(&sm.xtst[k][col8 + 4]);
            float s0 = sm.fs[row2][k];
            float s1 = sm.fs[row2 + 1][k];
            ull sp0 = pack2(s0, s0), sp1 = pack2(s1, s1);
            ffma2(a_[0][0], sp0, xq0.x); ffma2(a_[0][1], sp0, xq0.y);
            ffma2(a_[0][2], sp0, xq1.x); ffma2(a_[0][3], sp0, xq1.y);
            ffma2(a_[1][0], sp1, xq0.x); ffma2(a_[1][1], sp1, xq0.y);
            ffma2(a_[1][2], sp1, xq1.x); ffma2(a_[1][3], sp1, xq1.y);
        }

        {
            float4 nxa = *reinterpret_cast<const float4*>(&sm.nxts[col8]);
            float4 nxb = *reinterpret_cast<const float4*>(&sm.nxts[col8 + 4]);
            float nx[8] = {nxa.x, nxa.y, nxa.z, nxa.w, nxb.x, nxb.y, nxb.z, nxb.w};
#pragma unroll
            for (int r = 0; r < 2; r++) {
                int gi = i0 + row2 + r;
                bool valid = gi < N_;
                float nfv = sm.nfs[row2 + r];
                int lrow = sm.lidxs[row2 + r];
                float4 m0 = *reinterpret_cast<const float4*>(&sm.multT[lrow][col8]);
                float4 m1 = *reinterpret_cast<const float4*>(&sm.multT[lrow][col8 + 4]);
                float mv[8] = {m0.x, m0.y, m0.z, m0.w, m1.x, m1.y, m1.z, m1.w};
                float ev[8];
#pragma unroll
                for (int c2 = 0; c2 < 4; c2++) {
                    float d0, d1;
                    unpack2(a_[r][c2], d0, d1);
                    float r0 = fmaxf(nfv + nx[2 * c2]     - 2.f * d0, 0.f);
                    float r1 = fmaxf(nfv + nx[2 * c2 + 1] - 2.f * d1, 0.f);
                    ev[2 * c2]     = valid ? __expf(-r0) * mv[2 * c2]     : 0.f;
                    ev[2 * c2 + 1] = valid ? __expf(-r1) * mv[2 * c2 + 1] : 0.f;
                }
                *reinterpret_cast<float4*>(&sm.es[row2 + r][col8]) =
                    make_float4(ev[0], ev[1], ev[2], ev[3]);
                *reinterpret_cast<float4*>(&sm.es[row2 + r][col8 + 4]) =
                    make_float4(ev[4], ev[5], ev[6], ev[7]);
            }
        }

        if (c + 1 < nchunk) {
            int i0n = i0 + TI;
#pragma unroll
            for (int q = 0; q < 4; q++) {
                int gi = min(i0n + ld_r + q * 16, N_ - 1);
                pf_f[q] = *reinterpret_cast<const float4*>(f + gi * D_ + ld_k4);
            }
#pragma unroll
            for (int q = 0; q < 2; q++) {
                int idx = tid + q * 256, r = idx >> 3, k4 = (idx & 7) * 4;
                int gi = min(i0n + r, N_ - 1);
                pf_sl[q] = *reinterpret_cast<const float4*>(slb + gi * DY_ + k4);
            }
            pf_n = (tid < TI) ? nf[min(i0n + tid, N_ - 1)] : 0.f;
            pf_l = (tid < TI) ? li[min(i0n + tid, N_ - 1)] : 0;
        }
        __syncthreads();

        // accumulate: num[j][dy] += sl[i][dy] * e[i][j], 2j x 4dy
#pragma unroll 8
        for (int ii = 0; ii < TI; ii++) {
            float2 e2 = *reinterpret_cast<const float2*>(&sm.es[ii][jc2]);
            ull er0 = pack2(e2.x, e2.x), er1 = pack2(e2.y, e2.y);
            ulonglong2 slq = *reinterpret_cast<const ulonglong2*>(&sm.sls[ii][dy4]);
            ffma2(accn[0][0], er0, slq.x); ffma2(accn[0][1], er0, slq.y);
            ffma2(accn[1][0], er1, slq.x); ffma2(accn[1][1], er1, slq.y);
            if (dy4 == 0) { dn0 += e2.x; dn1 += e2.y; }
        }
        __syncthreads();

        if (c + 1 < nchunk) {
#pragma unroll
            for (int q = 0; q < 4; q++) {
                int r = ld_r + q * 16;
                sm.fs[r][ld_k4 + 0] = pf_f[q].x; sm.fs[r][ld_k4 + 1] = pf_f[q].y;
                sm.fs[r][ld_k4 + 2] = pf_f[q].z; sm.fs[r][ld_k4 + 3] = pf_f[q].w;
            }
#pragma unroll
            for (int q = 0; q < 2; q++) {
                int idx = tid + q * 256, r = idx >> 3, k4 = (idx & 7) * 4;
                *reinterpret_cast<float4*>(&sm.sls[r][k4]) = pf_sl[q];
            }
            if (tid < TI) { sm.nfs[tid] = pf_n; sm.lidxs[tid] = pf_l; }
            __syncthreads();
        }
    }

#pragma unroll
    for (int j = 0; j < 2; j++) {
        int jj = j0 + jc2 + j;
        float o[4];
        unpack2(accn[j][0], o[0], o[1]);
        unpack2(accn[j][1], o[2], o[3]);
        *reinterpret_cast<float4*>(&nump[slab][jj][dy4]) =
            make_float4(o[0], o[1], o[2], o[3]);
    }
    if (dy4 == 0) {
        denp[slab][j0 + jc2 + 0] = dn0;
        denp[slab][j0 + jc2 + 1] = dn1;
    }
}

// ---------------- K4: reduce partials, combine branches ----------------------
__global__ void k_out(float* __restrict__ out) {
    int gid = blockIdx.x * blockDim.x + threadIdx.x;
    if (gid >= B_ * DY_) return;
    int j = gid >> 5, dy = gid & 31;
    float n1 = 0.f, d1 = 0.f, n2 = 0.f, d2 = 0.f;
    for (int s = 0; s < NSLAB; s++) {
        n1 += g_num1_part[s][j][dy];
        d1 += g_den1_part[s][j];
        n2 += g_num2_part[s][j][dy];
        d2 += g_den2_part[s][j];
    }
    out[gid] = 0.5f * (n1 / d1 + n2 / d2);
}

// ---------------- launch -----------------------------------------------------
extern "C" void kernel_launch(void* const* d_in, const int* in_sizes, int n_in,
                              void* d_out, int out_size) {
    const float* x    = (const float*)d_in[0];
    const float* star = (const float*)d_in[1];
    const float* slb  = (const float*)d_in[2];
    const float* f1   = (const float*)d_in[3];
    const float* f2   = (const float*)d_in[4];
    const float* u1   = (const float*)d_in[5];
    const float* u2   = (const float*)d_in[6];
    const float* ld1  = (const float*)d_in[7];
    const float* ld2  = (const float*)d_in[8];
    const float* W1   = (const float*)d_in[9];
    const float* b1   = (const float*)d_in[10];
    const float* W2   = (const float*)d_in[11];
    const float* b2   = (const float*)d_in[12];
    const int*   li1  = (const int*)d_in[13];
    const int*   li2  = (const int*)d_in[14];
    float* out = (float*)d_out;

    cudaFuncSetAttribute(k_phaseA, cudaFuncAttributeMaxDynamicSharedMemorySize,
                         (int)sizeof(SmemA));
    cudaFuncSetAttribute(k_phaseC, cudaFuncAttributeMaxDynamicSharedMemorySize,
                         (int)sizeof(SmemC));

    k_prep<<<(B_ + 3 * N_ + 255) / 256, 256>>>(x, star, f1, f2);
    k_phaseA<<<dim3(B_ / TJ, NSLAB), 256, sizeof(SmemA)>>>(x, star, f1, f2);
    k_mid<<<B_, 128>>>(f1, f2, W1, b1, W2, b2, u1, u2);
    k_phaseC<<<dim3(B_ / TJ, NSLAB, 2), 256, sizeof(SmemC)>>>(f1, f2, slb, ld1, ld2, li1, li2);
    k_out<<<(B_ * DY_ + 255) / 256, 256>>>(out);
}

// round 4
// speedup vs baseline: 1.3362x; 1.3362x over previous
#include <cuda_runtime.h>
#include <cstdint>
#include <cfloat>

// Problem constants (fixed shapes for MergeNN_38903813767173)
#define B_ 2048
#define N_ 20000
#define D_ 64
#define DY_ 32
#define L_ 100
#define ETA_ 0.01f

#define TJ 64
#define TI 64
#define NSLAB 25
#define SLABROWS 800          // 25*800 = 20000 exactly; 13 chunks of 64 (tail 32)
#define NCHUNK 13
#define NSLAB2 (2 * NSLAB)    // phaseC partials split by i-parity

#define XAP 36                // split x/es tile stride (half-width 32 + pad)
#define SSP 68                // row-major star/f chunk stride (16B-aligned rows for cp.async)
#define MSP 68

typedef unsigned long long ull;

__device__ __forceinline__ ull pack2(float lo, float hi) {
    ull r; asm("mov.b64 %0, {%1, %2};" : "=l"(r) : "f"(lo), "f"(hi)); return r;
}
__device__ __forceinline__ void unpack2(ull v, float& lo, float& hi) {
    asm("mov.b64 {%0, %1}, %2;" : "=f"(lo), "=f"(hi) : "l"(v));
}
__device__ __forceinline__ void ffma2(ull& d, ull a, ull b) {
    asm("fma.rn.f32x2 %0, %1, %2, %0;" : "+l"(d) : "l"(a), "l"(b));
}
__device__ __forceinline__ unsigned su32(const void* p) {
    return (unsigned)__cvta_generic_to_shared(p);
}
#define CPA16(dst, src) \
    asm volatile("cp.async.ca.shared.global [%0], [%1], 16;" :: "r"(dst), "l"(src))
#define CP_COMMIT() asm volatile("cp.async.commit_group;")
#define CP_WAIT0()  asm volatile("cp.async.wait_group 0;" ::: "memory")

// ---------------- scratch (device globals; no allocations allowed) ----------
__device__ float g_nx[B_];
__device__ float g_ns[N_];
__device__ float g_nf1[N_];
__device__ float g_nf2[N_];
__device__ int   g_match[B_];

__device__ float g_esum_part[NSLAB][B_];
__device__ float g_acc1_part[NSLAB][B_][D_];
__device__ float g_acc2_part[NSLAB][B_][D_];

__device__ float g_xt1[B_][D_];
__device__ float g_xt2[B_][D_];
__device__ float g_nxt1[B_];
__device__ float g_nxt2[B_];
__device__ int   g_yidx1[B_];
__device__ int   g_yidx2[B_];

__device__ float g_num1_part[NSLAB2][B_][DY_];
__device__ float g_num2_part[NSLAB2][B_][DY_];
__device__ float g_den1_part[NSLAB2][B_];
__device__ float g_den2_part[NSLAB2][B_];

// ---------------- K0: squared norms + match init -----------------------------
__global__ void k_prep(const float* __restrict__ x, const float* __restrict__ star,
                       const float* __restrict__ f1, const float* __restrict__ f2) {
    int gid = blockIdx.x * blockDim.x + threadIdx.x;
    const float* src;
    float* dst;
    if (gid < B_) {
        g_match[gid] = 0x7fffffff;
        src = x + gid * D_;        dst = &g_nx[gid];
    } else if (gid < B_ + N_) {
        int r = gid - B_;          src = star + r * D_; dst = &g_ns[r];
    } else if (gid < B_ + 2 * N_) {
        int r = gid - B_ - N_;     src = f1 + r * D_;   dst = &g_nf1[r];
    } else if (gid < B_ + 3 * N_) {
        int r = gid - B_ - 2 * N_; src = f2 + r * D_;   dst = &g_nf2[r];
    } else {
        return;
    }
    float s = 0.f;
    const float4* p = reinterpret_cast<const float4*>(src);
#pragma unroll
    for (int i = 0; i < 16; i++) {
        float4 v = p[i];
        s += v.x * v.x + v.y * v.y + v.z * v.z + v.w * v.w;
    }
    *dst = s;
}

// ---------------- K1: phase A — e_star, esum, feats^T @ e_star ---------------
struct __align__(16) SmemA {
    float xA[D_][XAP];    // x tile cols with j&4==0, k-major, phys col (j>>3)*4+(j&3)
    float xB[D_][XAP];    // cols with j&4==4
    float nxs[TJ];
    float ss[TI][SSP];    // star chunk, row-major
    float nss[TI];
    float f1s[TI][D_];
    float f2s[TI][D_];
    float esA[TI][XAP];   // e cols j&4==0
    float esB[TI][XAP];
    float esred[16][SSP]; // esum partials [dg][j]
};

__global__ __launch_bounds__(256, 2)
void k_phaseA(const float* __restrict__ x, const float* __restrict__ star,
              const float* __restrict__ f1, const float* __restrict__ f2) {
    extern __shared__ char raw_[];
    SmemA& sm = *reinterpret_cast<SmemA*>(raw_);
    const int tid   = threadIdx.x;
    const int j0    = blockIdx.x * TJ;
    const int slab  = blockIdx.y;
    const int ibase = slab * SLABROWS;
    const int iend  = ibase + SLABROWS;

    // x tile: transpose into split k-major arrays (once per block)
    for (int idx = tid; idx < TJ * 16; idx += 256) {
        int j = idx >> 4, k4 = (idx & 15) * 4;
        float4 v = *reinterpret_cast<const float4*>(x + (j0 + j) * D_ + k4);
        float* arr = (j & 4) ? &sm.xB[0][0] : &sm.xA[0][0];
        int jp = (j >> 3) * 4 + (j & 3);
        arr[(k4 + 0) * XAP + jp] = v.x; arr[(k4 + 1) * XAP + jp] = v.y;
        arr[(k4 + 2) * XAP + jp] = v.z; arr[(k4 + 3) * XAP + jp] = v.w;
    }
    if (tid < TJ) sm.nxs[tid] = g_nx[j0 + tid];

    const int cg   = tid & 7;           // distance: cols cg*8..+7
    const int row2 = (tid >> 3) * 2;    // distance: rows row2, row2+1
    const int sid  = tid >> 7;          // accumulate: feature set
    const int jg   = tid & 7;           // accumulate: j block of 8
    const int dg   = (tid >> 3) & 15;   // accumulate: d block of 4
    const int dg4  = dg * 4;

    ull acc_[8][2];
#pragma unroll
    for (int a = 0; a < 8; a++) { acc_[a][0] = 0ull; acc_[a][1] = 0ull; }
    float esum8[8];
#pragma unroll
    for (int a = 0; a < 8; a++) esum8[a] = 0.f;

    const unsigned ss_b = su32(&sm.ss[0][0]);
    const unsigned f1_b = su32(&sm.f1s[0][0]);
    const unsigned f2_b = su32(&sm.f2s[0][0]);

    for (int c = 0; c < NCHUNK; c++) {
        const int i0 = ibase + c * TI;
        __syncthreads();   // previous consumers done / x-tile visible
        // tile loads via cp.async (12 x 16B per thread)
        for (int idx = tid; idx < TI * 16; idx += 256) {
            int r = idx >> 4, kb = (idx & 15) * 16;
            long gb = (long)min(i0 + r, N_ - 1) * 256;
            CPA16(ss_b + r * (SSP * 4) + kb, (const char*)star + gb + kb);
            CPA16(f1_b + r * 256 + kb, (const char*)f1 + gb + kb);
            CPA16(f2_b + r * 256 + kb, (const char*)f2 + gb + kb);
        }
        if (tid < TI) sm.nss[tid] = g_ns[min(i0 + tid, N_ - 1)];
        CP_COMMIT(); CP_WAIT0();
        __syncthreads();

        // --- distance: 2 rows x 8 cols, packed f32x2 ---
        ull a_[2][4];
#pragma unroll
        for (int r = 0; r < 2; r++)
#pragma unroll
            for (int cc = 0; cc < 4; cc++) a_[r][cc] = 0ull;
#pragma unroll 8
        for (int k = 0; k < D_; k++) {
            ulonglong2 xq0 = *reinterpret_cast<const ulonglong2*>(&sm.xA[k][cg * 4]);
            ulonglong2 xq1 = *reinterpret_cast<const ulonglong2*>(&sm.xB[k][cg * 4]);
            float s0 = sm.ss[row2][k];
            float s1 = sm.ss[row2 + 1][k];
            ull sp0 = pack2(s0, s0), sp1 = pack2(s1, s1);
            ffma2(a_[0][0], sp0, xq0.x); ffma2(a_[0][1], sp0, xq0.y);
            ffma2(a_[0][2], sp0, xq1.x); ffma2(a_[0][3], sp0, xq1.y);
            ffma2(a_[1][0], sp1, xq0.x); ffma2(a_[1][1], sp1, xq0.y);
            ffma2(a_[1][2], sp1, xq1.x); ffma2(a_[1][3], sp1, xq1.y);
        }
        {
            float4 nxa = *reinterpret_cast<const float4*>(&sm.nxs[cg * 8]);
            float4 nxb = *reinterpret_cast<const float4*>(&sm.nxs[cg * 8 + 4]);
            float nx[8] = {nxa.x, nxa.y, nxa.z, nxa.w, nxb.x, nxb.y, nxb.z, nxb.w};
#pragma unroll
            for (int r = 0; r < 2; r++) {
                int gi = i0 + row2 + r;
                bool valid = gi < iend;
                float ns = sm.nss[row2 + r];
                float ev[8];
#pragma unroll
                for (int c2 = 0; c2 < 4; c2++) {
                    float d0, d1;
                    // a_[r]: [0],[1] -> cols cg*8+0..3 ; [2],[3] -> cols cg*8+4..7
                    unpack2(a_[r][c2 < 2 ? c2 : c2], d0, d1);
                    int cbase = (c2 < 2) ? 2 * c2 : 4 + 2 * (c2 - 2);
                    float r0 = ns + nx[cbase]     - 2.f * d0;
                    float r1 = ns + nx[cbase + 1] - 2.f * d1;
                    if (valid && r0 <= 0.f) atomicMin(&g_match[j0 + cg * 8 + cbase], gi);
                    if (valid && r1 <= 0.f) atomicMin(&g_match[j0 + cg * 8 + cbase + 1], gi);
                    ev[cbase]     = valid ? __expf(-fmaxf(r0, 0.f)) : 0.f;
                    ev[cbase + 1] = valid ? __expf(-fmaxf(r1, 0.f)) : 0.f;
                }
                *reinterpret_cast<float4*>(&sm.esA[row2 + r][cg * 4]) =
                    make_float4(ev[0], ev[1], ev[2], ev[3]);
                *reinterpret_cast<float4*>(&sm.esB[row2 + r][cg * 4]) =
                    make_float4(ev[4], ev[5], ev[6], ev[7]);
            }
        }
        __syncthreads();   // es ready

        // --- accumulate: acc[j][d] += f[i][d]*e[i][j], 8j x 4d, set-split ---
        const float* fbase = sid ? &sm.f2s[0][0] : &sm.f1s[0][0];
#pragma unroll 4
        for (int i = 0; i < TI; i++) {
            float4 ea = *reinterpret_cast<const float4*>(&sm.esA[i][jg * 4]);
            float4 eb = *reinterpret_cast<const float4*>(&sm.esB[i][jg * 4]);
            ulonglong2 fq = *reinterpret_cast<const ulonglong2*>(fbase + i * D_ + dg4);
            ull e0 = pack2(ea.x, ea.x), e1 = pack2(ea.y, ea.y);
            ull e2 = pack2(ea.z, ea.z), e3 = pack2(ea.w, ea.w);
            ull e4 = pack2(eb.x, eb.x), e5 = pack2(eb.y, eb.y);
            ull e6 = pack2(eb.z, eb.z), e7 = pack2(eb.w, eb.w);
            ffma2(acc_[0][0], e0, fq.x); ffma2(acc_[0][1], e0, fq.y);
            ffma2(acc_[1][0], e1, fq.x); ffma2(acc_[1][1], e1, fq.y);
            ffma2(acc_[2][0], e2, fq.x); ffma2(acc_[2][1], e2, fq.y);
            ffma2(acc_[3][0], e3, fq.x); ffma2(acc_[3][1], e3, fq.y);
            ffma2(acc_[4][0], e4, fq.x); ffma2(acc_[4][1], e4, fq.y);
            ffma2(acc_[5][0], e5, fq.x); ffma2(acc_[5][1], e5, fq.y);
            ffma2(acc_[6][0], e6, fq.x); ffma2(acc_[6][1], e6, fq.y);
            ffma2(acc_[7][0], e7, fq.x); ffma2(acc_[7][1], e7, fq.y);
            if (sid == 0 && dg == (i & 15)) {
                esum8[0] += ea.x; esum8[1] += ea.y; esum8[2] += ea.z; esum8[3] += ea.w;
                esum8[4] += eb.x; esum8[5] += eb.y; esum8[6] += eb.z; esum8[7] += eb.w;
            }
        }
    }

    // write acc partials: logical j = j0 + jg*8 + jj
    {
        float (*accp)[B_][D_] = sid ? g_acc2_part : g_acc1_part;
#pragma unroll
        for (int jj = 0; jj < 8; jj++) {
            float o0, o1, o2, o3;
            unpack2(acc_[jj][0], o0, o1);
            unpack2(acc_[jj][1], o2, o3);
            *reinterpret_cast<float4*>(&accp[slab][j0 + jg * 8 + jj][dg4]) =
                make_float4(o0, o1, o2, o3);
        }
    }
    if (sid == 0) {
#pragma unroll
        for (int jj = 0; jj < 8; jj++) sm.esred[dg][jg * 8 + jj] = esum8[jj];
    }
    __syncthreads();
    if (tid < TJ) {
        float s = 0.f;
#pragma unroll
        for (int g = 0; g < 16; g++) s += sm.esred[g][tid];
        g_esum_part[slab][j0 + tid] = s;
    }
}

// ---------------- K2: middle — xt, y = xt@W+b, argmin label ------------------
__global__ __launch_bounds__(128)
void k_mid(const float* __restrict__ f1, const float* __restrict__ f2,
           const float* __restrict__ W1, const float* __restrict__ b1,
           const float* __restrict__ W2, const float* __restrict__ b2,
           const float* __restrict__ u1, const float* __restrict__ u2) {
    int j = blockIdx.x;
    int t = threadIdx.x;   // 128 threads

    __shared__ float xts[D_];
    __shared__ float ys[DY_];
    __shared__ float esum_s;
    __shared__ float ny_s;
    __shared__ float redv[128];
    __shared__ int   redi[128];

    int  mi = g_match[j];
    bool hm = (mi != 0x7fffffff);
    if (t == 0) {
        float s = 0.f;
        for (int k = 0; k < NSLAB; k++) s += g_esum_part[k][j];
        esum_s = s;
    }
    __syncthreads();

    for (int br = 0; br < 2; br++) {
        const float* f  = br ? f2 : f1;
        const float* W  = br ? W2 : W1;
        const float* bb = br ? b2 : b1;
        const float* u  = br ? u2 : u1;

        if (t < D_) {
            float a = 0.f;
            if (br) { for (int k = 0; k < NSLAB; k++) a += g_acc2_part[k][j][t]; }
            else    { for (int k = 0; k < NSLAB; k++) a += g_acc1_part[k][j][t]; }
            float v = hm ? f[mi * D_ + t] : a / esum_s;
            xts[t] = v;
            if (br) g_xt2[j][t] = v; else g_xt1[j][t] = v;
        }
        __syncthreads();
        if (t == 0) {
            float s = 0.f;
            for (int d = 0; d < D_; d++) s += xts[d] * xts[d];
            if (br) g_nxt2[j] = s; else g_nxt1[j] = s;
        }
        if (t < DY_) {
            float a = bb[t];
            for (int d = 0; d < D_; d++) a += xts[d] * W[d * DY_ + t];
            ys[t] = a;
        }
        __syncthreads();
        if (t == 0) {
            float s = 0.f;
            for (int dy = 0; dy < DY_; dy++) s += ys[dy] * ys[dy];
            ny_s = s;
        }
        __syncthreads();

        float v = FLT_MAX;
        int   vi = 0x7fffffff;
        if (t < L_) {
            float nu = 0.f, dot = 0.f;
            for (int dy = 0; dy < DY_; dy++) {
                float uu = u[t * DY_ + dy];
                nu += uu * uu;
                dot += uu * ys[dy];
            }
            v = fmaxf(ny_s + nu - 2.f * dot, 0.f);
            vi = t;
        }
        redv[t] = v; redi[t] = vi;
        __syncthreads();
        for (int off = 64; off > 0; off >>= 1) {
            if (t < off) {
                float v2 = redv[t + off]; int i2 = redi[t + off];
                if (v2 < redv[t] || (v2 == redv[t] && i2 < redi[t])) {
                    redv[t] = v2; redi[t] = i2;
                }
            }
            __syncthreads();
        }
        if (t == 0) { if (br) g_yidx2[j] = redi[0]; else g_yidx1[j] = redi[0]; }
        __syncthreads();
    }
}

// ---------------- K3: phase C — e2, labels^T @ e2 ---------------------------
struct __align__(16) SmemC {
    float multT[L_][MSP]; // exp(-eta*ld[l][yidx[j]])
    float xA[D_][XAP];    // xt tile split k-major
    float xB[D_][XAP];
    float nxts[TJ];
    int   yidxs[TJ];
    float fs[TI][SSP];
    float nfs[TI];
    int   lidxs[TI];
    float sls[TI][DY_];
    float esA[TI][XAP];
    float esB[TI][XAP];
    float denred[16][SSP]; // [par*8+dyg][j]
};

__global__ __launch_bounds__(256, 2)
void k_phaseC(const float* __restrict__ f1, const float* __restrict__ f2,
              const float* __restrict__ slb,
              const float* __restrict__ ld1, const float* __restrict__ ld2,
              const int* __restrict__ li1, const int* __restrict__ li2) {
    extern __shared__ char raw_[];
    SmemC& sm = *reinterpret_cast<SmemC*>(raw_);
    const int tid   = threadIdx.x;
    const int j0    = blockIdx.x * TJ;
    const int slab  = blockIdx.y;
    const int br    = blockIdx.z;
    const int ibase = slab * SLABROWS;
    const int iend  = ibase + SLABROWS;

    const float* f   = br ? f2 : f1;
    const float* ld  = br ? ld2 : ld1;
    const int*   li  = br ? li2 : li1;
    const float* nf  = br ? g_nf2 : g_nf1;
    const float (*xt)[D_] = br ? g_xt2 : g_xt1;
    const float* nxt = br ? g_nxt2 : g_nxt1;
    const int*   yix = br ? g_yidx2 : g_yidx1;
    float (*nump)[B_][DY_] = br ? g_num2_part : g_num1_part;
    float (*denp)[B_]      = br ? g_den2_part : g_den1_part;

    // xt tile split k-major
    for (int idx = tid; idx < TJ * 16; idx += 256) {
        int j = idx >> 4, k4 = (idx & 15) * 4;
        float4 v = *reinterpret_cast<const float4*>(&xt[j0 + j][k4]);
        float* arr = (j & 4) ? &sm.xB[0][0] : &sm.xA[0][0];
        int jp = (j >> 3) * 4 + (j & 3);
        arr[(k4 + 0) * XAP + jp] = v.x; arr[(k4 + 1) * XAP + jp] = v.y;
        arr[(k4 + 2) * XAP + jp] = v.z; arr[(k4 + 3) * XAP + jp] = v.w;
    }
    if (tid < TJ) { sm.nxts[tid] = nxt[j0 + tid]; sm.yidxs[tid] = yix[j0 + tid]; }
    __syncthreads();
    // multT: exp(-eta * ld[l][yidx[j]]), once per block
    for (int idx = tid; idx < L_ * TJ; idx += 256) {
        int l = idx >> 6, j = idx & 63;
        sm.multT[l][j] = __expf(-ETA_ * ld[l * L_ + sm.yidxs[j]]);
    }

    const int cg   = tid & 7;
    const int row2 = (tid >> 3) * 2;
    const int par  = tid >> 7;          // i-parity group
    const int t7   = tid & 127;
    const int jgc  = t7 & 15;           // 16 groups x 4 j
    const int dyg  = t7 >> 4;           // 8 groups x 4 dy
    const int dy4  = dyg * 4;

    ull accn[4][2];
#pragma unroll
    for (int a = 0; a < 4; a++) { accn[a][0] = 0ull; accn[a][1] = 0ull; }
    float4 den4 = make_float4(0.f, 0.f, 0.f, 0.f);

    const unsigned fs_b = su32(&sm.fs[0][0]);
    const unsigned sl_b = su32(&sm.sls[0][0]);

    for (int c = 0; c < NCHUNK; c++) {
        const int i0 = ibase + c * TI;
        __syncthreads();
        for (int idx = tid; idx < TI * 16; idx += 256) {
            int r = idx >> 4, kb = (idx & 15) * 16;
            long gb = (long)min(i0 + r, N_ - 1) * 256;
            CPA16(fs_b + r * (SSP * 4) + kb, (const char*)f + gb + kb);
        }
        for (int idx = tid; idx < TI * 8; idx += 256) {
            int r = idx >> 3, kb = (idx & 7) * 16;
            long gb = (long)min(i0 + r, N_ - 1) * 128;
            CPA16(sl_b + r * 128 + kb, (const char*)slb + gb + kb);
        }
        if (tid < TI) {
            int gi = min(i0 + tid, N_ - 1);
            sm.nfs[tid] = nf[gi];
            sm.lidxs[tid] = li[gi];
        }
        CP_COMMIT(); CP_WAIT0();
        __syncthreads();

        // --- distance ---
        ull a_[2][4];
#pragma unroll
        for (int r = 0; r < 2; r++)
#pragma unroll
            for (int cc = 0; cc < 4; cc++) a_[r][cc] = 0ull;
#pragma unroll 8
        for (int k = 0; k < D_; k++) {
            ulonglong2 xq0 = *reinterpret_cast<const ulonglong2*>(&sm.xA[k][cg * 4]);
            ulonglong2 xq1 = *reinterpret_cast<const ulonglong2*>(&sm.xB[k][cg * 4]);
            float s0 = sm.fs[row2][k];
            float s1 = sm.fs[row2 + 1][k];
            ull sp0 = pack2(s0, s0), sp1 = pack2(s1, s1);
            ffma2(a_[0][0], sp0, xq0.x); ffma2(a_[0][1], sp0, xq0.y);
            ffma2(a_[0][2], sp0, xq1.x); ffma2(a_[0][3], sp0, xq1.y);
            ffma2(a_[1][0], sp1, xq0.x); ffma2(a_[1][1], sp1, xq0.y);
            ffma2(a_[1][2], sp1, xq1.x); ffma2(a_[1][3], sp1, xq1.y);
        }
        {
            float4 nxa = *reinterpret_cast<const float4*>(&sm.nxts[cg * 8]);
            float4 nxb = *reinterpret_cast<const float4*>(&sm.nxts[cg * 8 + 4]);
            float nx[8] = {nxa.x, nxa.y, nxa.z, nxa.w, nxb.x, nxb.y, nxb.z, nxb.w};
#pragma unroll
            for (int r = 0; r < 2; r++) {
                int gi = i0 + row2 + r;
                bool valid = gi < iend;
                float nfv = sm.nfs[row2 + r];
                int lrow = sm.lidxs[row2 + r];
                float4 m0 = *reinterpret_cast<const float4*>(&sm.multT[lrow][cg * 8]);
                float4 m1 = *reinterpret_cast<const float4*>(&sm.multT[lrow][cg * 8 + 4]);
                float mv[8] = {m0.x, m0.y, m0.z, m0.w, m1.x, m1.y, m1.z, m1.w};
                float ev[8];
#pragma unroll
                for (int c2 = 0; c2 < 4; c2++) {
                    float d0, d1;
                    unpack2(a_[r][c2], d0, d1);
                    int cbase = (c2 < 2) ? 2 * c2 : 4 + 2 * (c2 - 2);
                    float r0 = fmaxf(nfv + nx[cbase]     - 2.f * d0, 0.f);
                    float r1 = fmaxf(nfv + nx[cbase + 1] - 2.f * d1, 0.f);
                    ev[cbase]     = valid ? __expf(-r0) * mv[cbase]     : 0.f;
                    ev[cbase + 1] = valid ? __expf(-r1) * mv[cbase + 1] : 0.f;
                }
                *reinterpret_cast<float4*>(&sm.esA[row2 + r][cg * 4]) =
                    make_float4(ev[0], ev[1], ev[2], ev[3]);
                *reinterpret_cast<float4*>(&sm.esB[row2 + r][cg * 4]) =
                    make_float4(ev[4], ev[5], ev[6], ev[7]);
            }
        }
        __syncthreads();

        // --- accumulate: num[j][dy] += sl[i][dy]*e[i][j], 4j x 4dy, i-parity split ---
        const float* ebase = (jgc & 1) ? &sm.esB[0][0] : &sm.esA[0][0];
        const int ecol = (jgc >> 1) * 4;
#pragma unroll 4
        for (int i = par; i < TI; i += 2) {
            float4 e4 = *reinterpret_cast<const float4*>(ebase + i * XAP + ecol);
            ulonglong2 slq = *reinterpret_cast<const ulonglong2*>(&sm.sls[i][dy4]);
            ull e0 = pack2(e4.x, e4.x), e1 = pack2(e4.y, e4.y);
            ull e2 = pack2(e4.z, e4.z), e3 = pack2(e4.w, e4.w);
            ffma2(accn[0][0], e0, slq.x); ffma2(accn[0][1], e0, slq.y);
            ffma2(accn[1][0], e1, slq.x); ffma2(accn[1][1], e1, slq.y);
            ffma2(accn[2][0], e2, slq.x); ffma2(accn[2][1], e2, slq.y);
            ffma2(accn[3][0], e3, slq.x); ffma2(accn[3][1], e3, slq.y);
            if (dyg == ((i >> 1) & 7)) {
                den4.x += e4.x; den4.y += e4.y; den4.z += e4.z; den4.w += e4.w;
            }
        }
    }

    // logical j for accumulate thread: j = jgc*4 + {0..3}?  No: split mapping.
    // ebase/ecol covers logical cols: jgc even -> esA phys (jgc>>1)*4 -> j = (jgc>>1)*8 + {0..3}
    //                                 jgc odd  -> esB phys (jgc>>1)*4 -> j = (jgc>>1)*8 + {4..7}
    const int jlog = (jgc >> 1) * 8 + (jgc & 1) * 4;
    const int slab2 = slab * 2 + par;
#pragma unroll
    for (int jj = 0; jj < 4; jj++) {
        float o0, o1, o2, o3;
        unpack2(accn[jj][0], o0, o1);
        unpack2(accn[jj][1], o2, o3);
        *reinterpret_cast<float4*>(&nump[slab2][j0 + jlog + jj][dy4]) =
            make_float4(o0, o1, o2, o3);
    }
    *reinterpret_cast<float4*>(&sm.denred[par * 8 + dyg][jlog]) = den4;
    __syncthreads();
    if (tid < TJ * 2) {
        int p = tid >> 6, j = tid & 63;
        float s = 0.f;
#pragma unroll
        for (int g = 0; g < 8; g++) s += sm.denred[p * 8 + g][j];
        denp[slab * 2 + p][j0 + j] = s;
    }
}

// ---------------- K4: reduce partials, combine branches ----------------------
__global__ void k_out(float* __restrict__ out) {
    int gid = blockIdx.x * blockDim.x + threadIdx.x;
    if (gid >= B_ * DY_) return;
    int j = gid >> 5, dy = gid & 31;
    float n1 = 0.f, d1 = 0.f, n2 = 0.f, d2 = 0.f;
    for (int s = 0; s < NSLAB2; s++) {
        n1 += g_num1_part[s][j][dy];
        d1 += g_den1_part[s][j];
        n2 += g_num2_part[s][j][dy];
        d2 += g_den2_part[s][j];
    }
    out[gid] = 0.5f * (n1 / d1 + n2 / d2);
}

// ---------------- launch -----------------------------------------------------
extern "C" void kernel_launch(void* const* d_in, const int* in_sizes, int n_in,
                              void* d_out, int out_size) {
    const float* x    = (const float*)d_in[0];
    const float* star = (const float*)d_in[1];
    const float* slb  = (const float*)d_in[2];
    const float* f1   = (const float*)d_in[3];
    const float* f2   = (const float*)d_in[4];
    const float* u1   = (const float*)d_in[5];
    const float* u2   = (const float*)d_in[6];
    const float* ld1  = (const float*)d_in[7];
    const float* ld2  = (const float*)d_in[8];
    const float* W1   = (const float*)d_in[9];
    const float* b1   = (const float*)d_in[10];
    const float* W2   = (const float*)d_in[11];
    const float* b2   = (const float*)d_in[12];
    const int*   li1  = (const int*)d_in[13];
    const int*   li2  = (const int*)d_in[14];
    float* out = (float*)d_out;

    cudaFuncSetAttribute(k_phaseA, cudaFuncAttributeMaxDynamicSharedMemorySize,
                         (int)sizeof(SmemA));
    cudaFuncSetAttribute(k_phaseC, cudaFuncAttributeMaxDynamicSharedMemorySize,
                         (int)sizeof(SmemC));

    k_prep<<<(B_ + 3 * N_ + 255) / 256, 256>>>(x, star, f1, f2);
    k_phaseA<<<dim3(B_ / TJ, NSLAB), 256, sizeof(SmemA)>>>(x, star, f1, f2);
    k_mid<<<B_, 128>>>(f1, f2, W1, b1, W2, b2, u1, u2);
    k_phaseC<<<dim3(B_ / TJ, NSLAB, 2), 256, sizeof(SmemC)>>>(f1, f2, slb, ld1, ld2, li1, li2);
    k_out<<<(B_ * DY_ + 255) / 256, 256>>>(out);
}